// round 11
// baseline (speedup 1.0000x reference)
#include <cuda_runtime.h>

#define NEG_INF __int_as_float(0xff800000)
#define SMEM_G3 (3*9216*4)
#define SMEM_AT ((4224+16896+16384+4224)*4)

__device__ float g_q[(size_t)4096*32*512];
__device__ float g_k[(size_t)4096*128*512];
__device__ float g_v[(size_t)4096*128*512];

__device__ __forceinline__ float to_tf32(float x){
    float y; asm("cvt.rna.tf32.f32 %0, %1;" : "=f"(y) : "f"(x)); return y;
}
__device__ __forceinline__ unsigned tfu(float x){ return __float_as_uint(to_tf32(x)); }
__device__ __forceinline__ float4 tf4(float4 v){
    v.x=to_tf32(v.x); v.y=to_tf32(v.y); v.z=to_tf32(v.z); v.w=to_tf32(v.w); return v;
}
__device__ __forceinline__ void mma8(float c[4], unsigned a0,unsigned a1,unsigned a2,unsigned a3,
                                     unsigned b0,unsigned b1){
    asm volatile("mma.sync.aligned.m16n8k8.row.col.f32.tf32.tf32.f32 "
                 "{%0,%1,%2,%3},{%4,%5,%6,%7},{%8,%9},{%0,%1,%2,%3};\n"
                 : "+f"(c[0]),"+f"(c[1]),"+f"(c[2]),"+f"(c[3])
                 : "r"(a0),"r"(a1),"r"(a2),"r"(a3),"r"(b0),"r"(b1));
}
__device__ __forceinline__ void cpa16(float* d, const float* s){
    unsigned a=(unsigned)__cvta_generic_to_shared(d);
    asm volatile("cp.async.ca.shared.global [%0], [%1], 16;\n" :: "r"(a),"l"(s));
}

// MODE 0: KV (Nd=1024 -> g_k/g_v)   MODE 1: Q (gathered rows -> g_q)
// 128 thr, tile 128x128, warp 64x64, 3-stage cp.async single-sync pipeline.
template<int MODE>
__device__ __forceinline__ void issue_tile(const float* __restrict__ A,
                                           const float* __restrict__ B,
                                           float* sm,int m0,int n0,int rbl,int c4,int kc,int s)
{
    float* dA = sm + s*9216; float* dB = dA + 4608;
    #pragma unroll
    for(int u=0;u<8;u++){
        int row = rbl + u*16;
        const float* as;
        if(MODE==1){ int rr=m0+row; as = A + ((size_t)(rr>>5)*128 + (rr&31))*256 + kc + c4; }
        else        { as = A + (size_t)(m0+row)*256 + kc + c4; }
        cpa16(&dA[row*36+c4], as);
        cpa16(&dB[row*36+c4], B + (size_t)(n0+row)*256 + kc + c4);
    }
    asm volatile("cp.async.commit_group;\n" ::: "memory");
}

template<int MODE>
__global__ __launch_bounds__(128,2)
void gemm2(const float* __restrict__ A, const float* __restrict__ B)
{
    extern __shared__ float sm[];
    const int tid=threadIdx.x, warp=tid>>5, lane=tid&31, g=lane>>2, t=lane&3;
    const int m0=blockIdx.y*128, n0=blockIdx.x*128;
    const int wr=(warp>>1)*64, wc=(warp&1)*64;
    const int rbl=tid>>3, c4=(tid&7)*4;
    float acc[4][8][4];
    #pragma unroll
    for(int a_=0;a_<4;a_++){ for(int j=0;j<8;j++){ for(int q=0;q<4;q++) acc[a_][j][q]=0.f; } }

    issue_tile<MODE>(A,B,sm,m0,n0,rbl,c4,0,0);
    issue_tile<MODE>(A,B,sm,m0,n0,rbl,c4,32,1);
    #pragma unroll
    for(int kc=0;kc<8;kc++){
        asm volatile("cp.async.wait_group 1;\n" ::: "memory");
        __syncthreads();
        const float* sA = sm + (kc%3)*9216; const float* sB = sA + 4608;
        #pragma unroll
        for(int ks=0;ks<4;ks++){
            int k0=ks*8;
            unsigned a[4][4];
            #pragma unroll
            for(int rb=0;rb<4;rb++){
                int r=wr+rb*16+g;
                a[rb][0]=tfu(sA[r*36+k0+t]);     a[rb][1]=tfu(sA[(r+8)*36+k0+t]);
                a[rb][2]=tfu(sA[r*36+k0+4+t]);   a[rb][3]=tfu(sA[(r+8)*36+k0+4+t]);
            }
            #pragma unroll
            for(int j=0;j<8;j++){
                int n=wc+j*8+g;
                unsigned b0=tfu(sB[n*36+k0+t]), b1=tfu(sB[n*36+k0+4+t]);
                #pragma unroll
                for(int rb=0;rb<4;rb++)
                    mma8(acc[rb][j],a[rb][0],a[rb][1],a[rb][2],a[rb][3],b0,b1);
            }
        }
        if(kc+2<8) issue_tile<MODE>(A,B,sm,m0,n0,rbl,c4,(kc+2)*32,(kc+2)%3);
        else asm volatile("cp.async.commit_group;\n" ::: "memory");  // keep group count uniform
    }
    #pragma unroll
    for(int rb=0;rb<4;rb++){
      #pragma unroll
      for(int j=0;j<8;j++){
        int n=n0+wc+j*8+2*t;
        #pragma unroll
        for(int h2=0;h2<2;h2++){
            int r=m0+wr+rb*16+g+h2*8;
            float2 v; v.x=acc[rb][j][h2*2]; v.y=acc[rb][j][h2*2+1];
            if(MODE==0){
                if(n<512) *(float2*)&g_k[(size_t)r*512+n]=v;
                else      *(float2*)&g_v[(size_t)r*512+(n-512)]=v;
            } else *(float2*)&g_q[(size_t)r*512+n]=v;
        }
      }
    }
}

// Fused attention + out-projection. One CTA per batch, 512 thr = 16 warps.
__global__ __launch_bounds__(512,1)
void attn_out(const unsigned* __restrict__ pmask, const unsigned* __restrict__ post,
              const float* __restrict__ Wout, const float* __restrict__ bias,
              float* __restrict__ out)
{
    extern __shared__ float sm[];
    float* sQ = sm;            // 32x132 (Q_h, then attnH)
    float* sK = sQ + 4224;     // 128x132 ; overlaid by sWb (2 x 512x12) in out-proj
    float* sV = sK + 16896;    // 128x128 swizzled
    float* sL = sV + 16384;    // 32x132
    float* sWb = sK;
    const int b=blockIdx.x;
    const int tid=threadIdx.x, warp=tid>>5, lane=tid&31, g=lane>>2, t=lane&3;
    const int r0=(warp>>3)*16, n0=(warp&7)*16;      // attention warp tile 16x16
    const int wr=r0, wn=(warp&7)*64;                 // out-proj warp tile 16x64
    const float scale=0.08838834764831845f;
    const unsigned* pm = pmask + (size_t)b*32*128;
    float o[8][4];
    #pragma unroll
    for(int j=0;j<8;j++){ for(int q=0;q<4;q++) o[j][q]=0.f; }

    for(int h=0;h<4;h++){
        const float* Qg = g_q + ((size_t)b*32 )*512 + h*128;
        const float* Kg = g_k + ((size_t)b*128)*512 + h*128;
        const float* Vg = g_v + ((size_t)b*128)*512 + h*128;
        #pragma unroll
        for(int u=0;u<2;u++){
            int i=tid+u*512, r=i>>5, c4=(i&31)*4;
            *(float4*)&sQ[r*132+c4] = tf4(*(const float4*)&Qg[(size_t)r*512+c4]);
        }
        #pragma unroll
        for(int u=0;u<8;u++){
            int i=tid+u*512, r=i>>5, c4=(i&31)*4;
            *(float4*)&sK[r*132+c4] = tf4(*(const float4*)&Kg[(size_t)r*512+c4]);
        }
        #pragma unroll
        for(int u=0;u<8;u++){
            int i=tid+u*512, k=i>>5, c4=(i&31)*4;
            *(float4*)&sV[k*128 + (c4 ^ ((k&3)<<3))] = tf4(*(const float4*)&Vg[(size_t)k*512+c4]);
        }
        __syncthreads();
        // ---- logits = Q @ K^T ----
        float cl[2][4]={};
        #pragma unroll
        for(int kk=0;kk<16;kk++){
            int k0=kk*8, r=r0+g;
            unsigned a0=__float_as_uint(sQ[r*132+k0+t]);
            unsigned a1=__float_as_uint(sQ[(r+8)*132+k0+t]);
            unsigned a2=__float_as_uint(sQ[r*132+k0+4+t]);
            unsigned a3=__float_as_uint(sQ[(r+8)*132+k0+4+t]);
            #pragma unroll
            for(int j=0;j<2;j++){
                int n=n0+j*8+g;
                unsigned b0=__float_as_uint(sK[n*132+k0+t]);
                unsigned b1=__float_as_uint(sK[n*132+k0+4+t]);
                mma8(cl[j],a0,a1,a2,a3,b0,b1);
            }
        }
        #pragma unroll
        for(int j=0;j<2;j++){
            int n=n0+j*8+2*t;
            #pragma unroll
            for(int h2=0;h2<2;h2++){
                int r=r0+g+h2*8;
                float x0=cl[j][h2*2]*scale, x1=cl[j][h2*2+1]*scale;
                if(pm[r*128+n  ]!=0u) x0=NEG_INF;
                if(pm[r*128+n+1]!=0u) x1=NEG_INF;
                sL[r*132+n]=x0; sL[r*132+n+1]=x1;
            }
        }
        __syncthreads();
        // ---- softmax: 2 rows per warp ----
        #pragma unroll
        for(int rr=0;rr<2;rr++){
            int r=warp*2+rr;
            float x[4];
            #pragma unroll
            for(int i2=0;i2<4;i2++) x[i2]=sL[r*132+lane+32*i2];
            float m=fmaxf(fmaxf(x[0],x[1]),fmaxf(x[2],x[3]));
            #pragma unroll
            for(int oo=16;oo>0;oo>>=1) m=fmaxf(m,__shfl_xor_sync(0xffffffffu,m,oo));
            bool dead=(m==NEG_INF);
            float p[4], s=0.f;
            #pragma unroll
            for(int i2=0;i2<4;i2++){ p[i2]=dead?0.f:__expf(x[i2]-m); s+=p[i2]; }
            #pragma unroll
            for(int oo=16;oo>0;oo>>=1) s+=__shfl_xor_sync(0xffffffffu,s,oo);
            float inv=(s>0.f)?(1.f/s):0.f;
            #pragma unroll
            for(int i2=0;i2<4;i2++) sL[r*132+lane+32*i2]=to_tf32(p[i2]*inv);
        }
        __syncthreads();
        // ---- attnH = P @ V  (into sQ; Q already consumed) ----
        float co[2][4]={};
        #pragma unroll
        for(int kk=0;kk<16;kk++){
            int k0=kk*8, r=r0+g;
            unsigned a0=__float_as_uint(sL[r*132+k0+t]);
            unsigned a1=__float_as_uint(sL[(r+8)*132+k0+t]);
            unsigned a2=__float_as_uint(sL[r*132+k0+4+t]);
            unsigned a3=__float_as_uint(sL[(r+8)*132+k0+4+t]);
            #pragma unroll
            for(int j=0;j<2;j++){
                int n=(n0+j*8+g) ^ (t<<3);
                unsigned b0=__float_as_uint(sV[(k0+t  )*128 + n]);
                unsigned b1=__float_as_uint(sV[(k0+4+t)*128 + n]);
                mma8(co[j],a0,a1,a2,a3,b0,b1);
            }
        }
        #pragma unroll
        for(int j=0;j<2;j++){
            int n=n0+j*8+2*t;
            #pragma unroll
            for(int h2=0;h2<2;h2++){
                int r=r0+g+h2*8;
                sQ[r*132+n]=co[j][h2*2]; sQ[r*132+n+1]=co[j][h2*2+1];
            }
        }
        // ---- out += attnH @ Wout[:, h*128:+128]^T  (Wb streamed, 2-stage) ----
        {   const float* src0 = Wout + (size_t)tid*512 + h*128;
            cpa16(&sWb[tid*12  ], src0);
            cpa16(&sWb[tid*12+4], src0+4);
            asm volatile("cp.async.commit_group;\n" ::: "memory");
            #pragma unroll
            for(int kc=0;kc<16;kc++){
                if(kc<15){
                    int s=(kc+1)&1;
                    const float* src = Wout + (size_t)tid*512 + h*128 + (kc+1)*8;
                    cpa16(&sWb[s*6144 + tid*12  ], src);
                    cpa16(&sWb[s*6144 + tid*12+4], src+4);
                    asm volatile("cp.async.commit_group;\n" ::: "memory");
                    asm volatile("cp.async.wait_group 1;\n" ::: "memory");
                } else asm volatile("cp.async.wait_group 0;\n" ::: "memory");
                __syncthreads();
                int s=kc&1, r=wr+g;
                unsigned a0=tfu(sQ[r*132 + kc*8 + t]);
                unsigned a1=tfu(sQ[(r+8)*132 + kc*8 + t]);
                unsigned a2=tfu(sQ[r*132 + kc*8 + 4 + t]);
                unsigned a3=tfu(sQ[(r+8)*132 + kc*8 + 4 + t]);
                #pragma unroll
                for(int j=0;j<8;j++){
                    int n=wn+j*8+g;
                    unsigned b0=tfu(sWb[s*6144 + n*12 + t]);
                    unsigned b1=tfu(sWb[s*6144 + n*12 + 4 + t]);
                    mma8(o[j],a0,a1,a2,a3,b0,b1);
                }
                __syncthreads();
            }
        }
    }
    // ---- epilogue: bias + post-mask + store ----
    #pragma unroll
    for(int j=0;j<8;j++){
        int n=wn+j*8+2*t;
        float b0v=bias[n], b1v=bias[n+1];
        #pragma unroll
        for(int h2=0;h2<2;h2++){
            int r=wr+g+h2*8;
            float2 v; v.x=o[j][h2*2]+b0v; v.y=o[j][h2*2+1]+b1v;
            if(post[b*32+r]!=0u){ v.x=0.f; v.y=0.f; }
            *(float2*)&out[((size_t)b*32+r)*512 + n]=v;
        }
    }
}

extern "C" void kernel_launch(void* const* d_in, const int* in_sizes, int n_in,
                              void* d_out, int out_size)
{
    const float*    ent   = (const float*)d_in[0];
    const unsigned* pmask = (const unsigned*)d_in[1];
    const unsigned* post  = (const unsigned*)d_in[2];
    const float*    Win   = (const float*)d_in[3];
    const float*    Wout  = (const float*)d_in[4];
    const float*    bout  = (const float*)d_in[5];
    float*          out   = (float*)d_out;
    (void)in_sizes; (void)n_in; (void)out_size;

    cudaFuncSetAttribute(gemm2<0>, cudaFuncAttributeMaxDynamicSharedMemorySize, SMEM_G3);
    cudaFuncSetAttribute(gemm2<1>, cudaFuncAttributeMaxDynamicSharedMemorySize, SMEM_G3);
    cudaFuncSetAttribute(attn_out, cudaFuncAttributeMaxDynamicSharedMemorySize, SMEM_AT);

    // K1a: K/V projection  [524288 x 1024]
    gemm2<0><<<dim3(8,4096),128,SMEM_G3>>>(ent, Win + 512*256);
    // K1b: Q projection    [131072 x 512] (gathered rows)
    gemm2<1><<<dim3(4,1024),128,SMEM_G3>>>(ent, Win);
    // K2: fused attention + out-projection + bias + post-mask
    attn_out<<<4096,512,SMEM_AT>>>(pmask, post, Wout, bout, out);
}

// round 12
// speedup vs baseline: 1.4577x; 1.4577x over previous
#include <cuda_runtime.h>

#define NEG_INF __int_as_float(0xff800000)
#define SMEM_ATTN ((32*132 + 128*132 + 128*128 + 32*132)*4)
#define SMEM_GEMM (2*2*128*36*4)

__device__ float g_q[(size_t)4096*32*512];
__device__ float g_k[(size_t)4096*128*512];
__device__ float g_v[(size_t)4096*128*512];
__device__ float g_attn[(size_t)4096*32*512];

__device__ __forceinline__ float to_tf32(float x){
    float y; asm("cvt.rna.tf32.f32 %0, %1;" : "=f"(y) : "f"(x)); return y;
}
__device__ __forceinline__ unsigned tfu(float x){ return __float_as_uint(to_tf32(x)); }
__device__ __forceinline__ void mma8(float c[4], unsigned a0,unsigned a1,unsigned a2,unsigned a3,
                                     unsigned b0,unsigned b1){
    asm volatile("mma.sync.aligned.m16n8k8.row.col.f32.tf32.tf32.f32 "
                 "{%0,%1,%2,%3},{%4,%5,%6,%7},{%8,%9},{%0,%1,%2,%3};\n"
                 : "+f"(c[0]),"+f"(c[1]),"+f"(c[2]),"+f"(c[3])
                 : "r"(a0),"r"(a1),"r"(a2),"r"(a3),"r"(b0),"r"(b1));
}
__device__ __forceinline__ void cpa16(float* d, const float* s){
    unsigned a=(unsigned)__cvta_generic_to_shared(d);
    asm volatile("cp.async.ca.shared.global [%0], [%1], 16;\n" :: "r"(a),"l"(s));
}
#define CP_COMMIT() asm volatile("cp.async.commit_group;\n" ::: "memory")
#define CP_WAIT(n)  asm volatile("cp.async.wait_group %0;\n" :: "n"(n) : "memory")

// MODE 0: KV  (A=entities, B=Win+512*256, Nd=1024 -> g_k/g_v)
// MODE 1: Q   (A=entities gathered rows b*32+q,   Nd=512 -> g_q)
// MODE 2: OUT (A=g_attn, B=Wout, Nd=512, bias+rowmask -> Cp)
// 128 threads, CTA tile 128x128, warp tile 64x64, cp.async 2-stage. (R9 proven form)
template<int MODE,int KD>
__device__ __forceinline__ void issue_tile(const float* __restrict__ A,
                                           const float* __restrict__ B,
                                           float* sm, int m0,int n0,int rbl,int c4,
                                           int kc,int s)
{
    float* dA = sm + s*9216;
    float* dB = dA + 4608;
    #pragma unroll
    for(int u=0;u<8;u++){
        int row = rbl + u*16;
        const float* as;
        if(MODE==1){ int rr=m0+row; as = A + ((size_t)(rr>>5)*128 + (rr&31))*256 + kc + c4; }
        else if(MODE==0){ as = A + (size_t)(m0+row)*256 + kc + c4; }
        else { as = g_attn + (size_t)(m0+row)*512 + kc + c4; }
        cpa16(&dA[row*36+c4], as);
        cpa16(&dB[row*36+c4], B + (size_t)(n0+row)*KD + kc + c4);
    }
    CP_COMMIT();
}

template<int MODE,int KD>
__global__ __launch_bounds__(128,2)
void gemm2(const float* __restrict__ A, const float* __restrict__ B,
           float* __restrict__ Cp, const float* __restrict__ bias,
           const unsigned* __restrict__ rmask)
{
    extern __shared__ float sm[];
    const int tid=threadIdx.x, warp=tid>>5, lane=tid&31, g=lane>>2, t=lane&3;
    const int m0=blockIdx.y*128, n0=blockIdx.x*128;
    const int wr=(warp>>1)*64, wc=(warp&1)*64;
    const int rbl=tid>>3, c4=(tid&7)*4;
    float acc[4][8][4];
    #pragma unroll
    for(int a_=0;a_<4;a_++){ for(int j=0;j<8;j++){ for(int q=0;q<4;q++) acc[a_][j][q]=0.f; } }

    const int NK = KD/32;
    issue_tile<MODE,KD>(A,B,sm,m0,n0,rbl,c4,0,0);
    for(int kc=0;kc<NK;kc++){
        if(kc+1<NK){
            issue_tile<MODE,KD>(A,B,sm,m0,n0,rbl,c4,(kc+1)*32,(kc+1)&1);
            CP_WAIT(1);
        } else {
            CP_WAIT(0);
        }
        __syncthreads();
        const float* sA = sm + (kc&1)*9216;
        const float* sB = sA + 4608;
        #pragma unroll
        for(int ks=0;ks<4;ks++){
            int k0=ks*8;
            unsigned a[4][4];
            #pragma unroll
            for(int rb=0;rb<4;rb++){
                int r=wr+rb*16+g;
                a[rb][0]=tfu(sA[r*36+k0+t]);
                a[rb][1]=tfu(sA[(r+8)*36+k0+t]);
                a[rb][2]=tfu(sA[r*36+k0+4+t]);
                a[rb][3]=tfu(sA[(r+8)*36+k0+4+t]);
            }
            #pragma unroll
            for(int j=0;j<8;j++){
                int n=wc+j*8+g;
                unsigned b0=tfu(sB[n*36+k0+t]);
                unsigned b1=tfu(sB[n*36+k0+4+t]);
                #pragma unroll
                for(int rb=0;rb<4;rb++)
                    mma8(acc[rb][j],a[rb][0],a[rb][1],a[rb][2],a[rb][3],b0,b1);
            }
        }
        __syncthreads();
    }
    #pragma unroll
    for(int rb=0;rb<4;rb++){
      #pragma unroll
      for(int j=0;j<8;j++){
        int n=n0+wc+j*8+2*t;
        float b0v=0.f,b1v=0.f;
        if(MODE==2){ b0v=bias[n]; b1v=bias[n+1]; }
        #pragma unroll
        for(int h2=0;h2<2;h2++){
            int r=m0+wr+rb*16+g+h2*8;
            float2 v; v.x=acc[rb][j][h2*2]+b0v; v.y=acc[rb][j][h2*2+1]+b1v;
            if(MODE==0){
                if(n<512) *(float2*)&g_k[(size_t)r*512+n]=v;
                else      *(float2*)&g_v[(size_t)r*512+(n-512)]=v;
            } else if(MODE==1){
                *(float2*)&g_q[(size_t)r*512+n]=v;
            } else {
                if(rmask[r]!=0u){ v.x=0.f; v.y=0.f; }
                *(float2*)&Cp[(size_t)r*512+n]=v;
            }
        }
      }
    }
}

// One CTA per (batch, head). 512 thr = 16 warps, warp tile 16x16.
// cp.async staging: group0={Q,K}, group1={V}; V arrival overlapped with QK+softmax.
__global__ __launch_bounds__(512,1)
void attn_kernel(const unsigned* __restrict__ pmask)
{
    extern __shared__ float sm[];
    float* sQ = sm;                  // 32x132 (raw fp32; tf32 at fragment load)
    float* sK = sQ + 32*132;         // 128x132
    float* sV = sK + 128*132;        // 128x128, natural [e][d], XOR-swizzled cols
    float* sL = sV + 128*128;        // 32x132
    int b=blockIdx.x, h=blockIdx.y;
    int tid=threadIdx.x, warp=tid>>5, lane=tid&31, g=lane>>2, t=lane&3;
    const float* Qg = g_q + ((size_t)b*32 )*512 + h*128;
    const float* Kg = g_k + ((size_t)b*128)*512 + h*128;
    const float* Vg = g_v + ((size_t)b*128)*512 + h*128;

    #pragma unroll
    for(int u=0;u<2;u++){
        int i=tid+u*512, r=i>>5, c4=(i&31)*4;
        cpa16(&sQ[r*132+c4], &Qg[(size_t)r*512+c4]);
    }
    #pragma unroll
    for(int u=0;u<8;u++){
        int i=tid+u*512, r=i>>5, c4=(i&31)*4;
        cpa16(&sK[r*132+c4], &Kg[(size_t)r*512+c4]);
    }
    CP_COMMIT();
    #pragma unroll
    for(int u=0;u<8;u++){
        int i=tid+u*512, k=i>>5, c4=(i&31)*4;
        cpa16(&sV[k*128 + (c4 ^ ((k&3)<<3))], &Vg[(size_t)k*512+c4]);
    }
    CP_COMMIT();
    CP_WAIT(1);              // Q,K ready; V still in flight
    __syncthreads();

    int r0=(warp>>3)*16, n0=(warp&7)*16;
    // ---- logits = Q @ K^T ----
    float cl[2][4]={};
    #pragma unroll
    for(int kk=0;kk<16;kk++){
        int k0=kk*8, r=r0+g;
        unsigned a0=tfu(sQ[r*132+k0+t]);
        unsigned a1=tfu(sQ[(r+8)*132+k0+t]);
        unsigned a2=tfu(sQ[r*132+k0+4+t]);
        unsigned a3=tfu(sQ[(r+8)*132+k0+4+t]);
        #pragma unroll
        for(int j=0;j<2;j++){
            int n=n0+j*8+g;
            unsigned b0=tfu(sK[n*132+k0+t]);
            unsigned b1=tfu(sK[n*132+k0+4+t]);
            mma8(cl[j],a0,a1,a2,a3,b0,b1);
        }
    }
    const float scale=0.08838834764831845f;
    const unsigned* pm = pmask + (size_t)b*32*128;
    #pragma unroll
    for(int j=0;j<2;j++){
        int n=n0+j*8+2*t;
        #pragma unroll
        for(int h2=0;h2<2;h2++){
            int r=r0+g+h2*8;
            float x0=cl[j][h2*2]*scale, x1=cl[j][h2*2+1]*scale;
            if(pm[r*128+n  ]!=0u) x0=NEG_INF;
            if(pm[r*128+n+1]!=0u) x1=NEG_INF;
            sL[r*132+n]=x0; sL[r*132+n+1]=x1;
        }
    }
    __syncthreads();
    // ---- softmax: 2 rows per warp ----
    #pragma unroll
    for(int rr=0;rr<2;rr++){
        int r=warp*2+rr;
        float x[4];
        #pragma unroll
        for(int i2=0;i2<4;i2++) x[i2]=sL[r*132+lane+32*i2];
        float m=fmaxf(fmaxf(x[0],x[1]),fmaxf(x[2],x[3]));
        #pragma unroll
        for(int o=16;o>0;o>>=1) m=fmaxf(m,__shfl_xor_sync(0xffffffffu,m,o));
        bool dead=(m==NEG_INF);
        float p[4], s=0.f;
        #pragma unroll
        for(int i2=0;i2<4;i2++){ p[i2]=dead?0.f:__expf(x[i2]-m); s+=p[i2]; }
        #pragma unroll
        for(int o=16;o>0;o>>=1) s+=__shfl_xor_sync(0xffffffffu,s,o);
        float inv=(s>0.f)?(1.f/s):0.f;
        #pragma unroll
        for(int i2=0;i2<4;i2++) sL[r*132+lane+32*i2]=to_tf32(p[i2]*inv);
    }
    CP_WAIT(0);              // V landed (each thread's own group; barrier publishes)
    __syncthreads();
    // ---- out = P @ V (V natural layout, swizzled B-fragment) ----
    float co[2][4]={};
    #pragma unroll
    for(int kk=0;kk<16;kk++){
        int k0=kk*8, r=r0+g;
        unsigned a0=__float_as_uint(sL[r*132+k0+t]);
        unsigned a1=__float_as_uint(sL[(r+8)*132+k0+t]);
        unsigned a2=__float_as_uint(sL[r*132+k0+4+t]);
        unsigned a3=__float_as_uint(sL[(r+8)*132+k0+4+t]);
        #pragma unroll
        for(int j=0;j<2;j++){
            int n=(n0+j*8+g) ^ (t<<3);
            unsigned b0=tfu(sV[(k0+t  )*128 + n]);
            unsigned b1=tfu(sV[(k0+4+t)*128 + n]);
            mma8(co[j],a0,a1,a2,a3,b0,b1);
        }
    }
    #pragma unroll
    for(int j=0;j<2;j++){
        int n=n0+j*8+2*t;
        #pragma unroll
        for(int h2=0;h2<2;h2++){
            int r=r0+g+h2*8;
            float2 v; v.x=co[j][h2*2]; v.y=co[j][h2*2+1];
            *(float2*)&g_attn[((size_t)b*32+r)*512 + h*128 + n]=v;
        }
    }
}

extern "C" void kernel_launch(void* const* d_in, const int* in_sizes, int n_in,
                              void* d_out, int out_size)
{
    const float*    ent   = (const float*)d_in[0];
    const unsigned* pmask = (const unsigned*)d_in[1];
    const unsigned* post  = (const unsigned*)d_in[2];
    const float*    Win   = (const float*)d_in[3];
    const float*    Wout  = (const float*)d_in[4];
    const float*    bout  = (const float*)d_in[5];
    float*          out   = (float*)d_out;
    (void)in_sizes; (void)n_in; (void)out_size;

    cudaFuncSetAttribute(gemm2<0,256>, cudaFuncAttributeMaxDynamicSharedMemorySize, SMEM_GEMM);
    cudaFuncSetAttribute(gemm2<1,256>, cudaFuncAttributeMaxDynamicSharedMemorySize, SMEM_GEMM);
    cudaFuncSetAttribute(gemm2<2,512>, cudaFuncAttributeMaxDynamicSharedMemorySize, SMEM_GEMM);
    cudaFuncSetAttribute(attn_kernel,  cudaFuncAttributeMaxDynamicSharedMemorySize, SMEM_ATTN);

    // K1a: K/V projection  [524288 x 1024] = ent @ (Win rows 512..1535)^T
    gemm2<0,256><<<dim3(8,4096),128,SMEM_GEMM>>>(ent, Win + 512*256, nullptr, nullptr, nullptr);
    // K1b: Q projection    [131072 x 512]  = ent[b,0:32] @ (Win rows 0..511)^T
    gemm2<1,256><<<dim3(4,1024),128,SMEM_GEMM>>>(ent, Win, nullptr, nullptr, nullptr);
    // K2: per-(batch,head) masked attention (cp.async overlapped)
    attn_kernel<<<dim3(4096,4),512,SMEM_ATTN>>>(pmask);
    // K3: out projection   [131072 x 512] @ Wout^T + bias, post-mask
    gemm2<2,512><<<dim3(4,1024),128,SMEM_GEMM>>>(nullptr, Wout, out, bout, post);
}

// round 15
// speedup vs baseline: 1.5479x; 1.0619x over previous
#include <cuda_runtime.h>

#define NEG_INF __int_as_float(0xff800000)
#define SMEM_ATTN ((32*132 + 128*132 + 128*128 + 32*132)*4)
#define SMEM_GEMM (2*2*128*36*4)

__device__ float g_q[(size_t)4096*32*512];
__device__ float g_k[(size_t)4096*128*512];
__device__ float g_v[(size_t)4096*128*512];
__device__ float g_attn[(size_t)4096*32*512];
__device__ float g_win[1536*256];
__device__ float g_wout[512*512];

__device__ __forceinline__ float to_tf32(float x){
    float y; asm("cvt.rna.tf32.f32 %0, %1;" : "=f"(y) : "f"(x)); return y;
}
__device__ __forceinline__ unsigned tfu(float x){ return __float_as_uint(to_tf32(x)); }
__device__ __forceinline__ float4 tf4(float4 v){
    v.x=to_tf32(v.x); v.y=to_tf32(v.y); v.z=to_tf32(v.z); v.w=to_tf32(v.w); return v;
}
__device__ __forceinline__ void mma8(float c[4], unsigned a0,unsigned a1,unsigned a2,unsigned a3,
                                     unsigned b0,unsigned b1){
    asm volatile("mma.sync.aligned.m16n8k8.row.col.f32.tf32.tf32.f32 "
                 "{%0,%1,%2,%3},{%4,%5,%6,%7},{%8,%9},{%0,%1,%2,%3};\n"
                 : "+f"(c[0]),"+f"(c[1]),"+f"(c[2]),"+f"(c[3])
                 : "r"(a0),"r"(a1),"r"(a2),"r"(a3),"r"(b0),"r"(b1));
}
__device__ __forceinline__ void cpa16(float* d, const float* s){
    unsigned a=(unsigned)__cvta_generic_to_shared(d);
    asm volatile("cp.async.ca.shared.global [%0], [%1], 16;\n" :: "r"(a),"l"(s));
}
#define CP_COMMIT() asm volatile("cp.async.commit_group;\n" ::: "memory")
#define CP_WAIT(n)  asm volatile("cp.async.wait_group %0;\n" :: "n"(n) : "memory")

// Round weights to tf32 once (operands must be pre-rounded for cvt-free inner loops).
__global__ void prep_w(const float* __restrict__ Win, const float* __restrict__ Wout){
    int i = blockIdx.x*256 + threadIdx.x;
    if(i < 1536*256/4) ((float4*)g_win)[i]  = tf4(((const float4*)Win)[i]);
    if(i < 512*512/4)  ((float4*)g_wout)[i] = tf4(((const float4*)Wout)[i]);
}

// MODE 0: KV (A=entities, B=g_win rows 512.., Nd=1024 -> g_k/g_v, rounded)
// MODE 1: Q  (A=entities gathered rows,  B=g_win rows 0..511 -> g_q, rounded)
// MODE 2: OUT(A=g_attn(pre-rounded), B=g_wout, bias+rowmask -> Cp, full fp32)
// 128 thr, CTA tile 128x128, warp 64x64, cp.async 2-stage + fragment double-buffer.
template<int MODE,int KD>
__device__ __forceinline__ void issue_tile(const float* __restrict__ A,
                                           float* sm, int m0,int n0,int rbl,int c4,
                                           int kc,int s)
{
    float* dA = sm + s*9216;
    float* dB = dA + 4608;
    #pragma unroll
    for(int u=0;u<8;u++){
        int row = rbl + u*16;
        const float *as, *bs;
        if(MODE==1){ int rr=m0+row; as = A + ((size_t)(rr>>5)*128 + (rr&31))*256 + kc + c4;
                     bs = g_win + (size_t)(n0+row)*256 + kc + c4; }
        else if(MODE==0){ as = A + (size_t)(m0+row)*256 + kc + c4;
                          bs = g_win + (size_t)(512+n0+row)*256 + kc + c4; }
        else { as = g_attn + (size_t)(m0+row)*512 + kc + c4;
               bs = g_wout + (size_t)(n0+row)*512 + kc + c4; }
        cpa16(&dA[row*36+c4], as);
        cpa16(&dB[row*36+c4], bs);
    }
    CP_COMMIT();
}

template<int MODE>
__device__ __forceinline__ void loadA(unsigned a[4][4], const float* sA,int wr,int g,int t,int k0){
    #pragma unroll
    for(int rb=0;rb<4;rb++){
        int r=wr+rb*16+g;
        float x0=sA[r*36+k0+t],   x1=sA[(r+8)*36+k0+t];
        float x2=sA[r*36+k0+4+t], x3=sA[(r+8)*36+k0+4+t];
        if(MODE<2){ a[rb][0]=tfu(x0); a[rb][1]=tfu(x1); a[rb][2]=tfu(x2); a[rb][3]=tfu(x3); }
        else { a[rb][0]=__float_as_uint(x0); a[rb][1]=__float_as_uint(x1);
               a[rb][2]=__float_as_uint(x2); a[rb][3]=__float_as_uint(x3); }
    }
}

template<int MODE,int KD>
__global__ __launch_bounds__(128,2)
void gemm2(const float* __restrict__ A, float* __restrict__ Cp,
           const float* __restrict__ bias, const unsigned* __restrict__ rmask)
{
    extern __shared__ float sm[];
    const int tid=threadIdx.x, warp=tid>>5, lane=tid&31, g=lane>>2, t=lane&3;
    const int m0=blockIdx.y*128, n0=blockIdx.x*128;
    const int wr=(warp>>1)*64, wc=(warp&1)*64;
    const int rbl=tid>>3, c4=(tid&7)*4;
    float acc[4][8][4];
    #pragma unroll
    for(int a_=0;a_<4;a_++){ for(int j=0;j<8;j++){ for(int q=0;q<4;q++) acc[a_][j][q]=0.f; } }

    const int NK = KD/32;
    issue_tile<MODE,KD>(A,sm,m0,n0,rbl,c4,0,0);
    for(int kc=0;kc<NK;kc++){
        if(kc+1<NK){
            issue_tile<MODE,KD>(A,sm,m0,n0,rbl,c4,(kc+1)*32,(kc+1)&1);
            CP_WAIT(1);
        } else {
            CP_WAIT(0);
        }
        __syncthreads();
        const float* sA = sm + (kc&1)*9216;
        const float* sB = sA + 4608;
        unsigned afr[2][4][4];
        loadA<MODE>(afr[0], sA, wr,g,t, 0);
        #pragma unroll
        for(int ks=0;ks<4;ks++){
            if(ks<3) loadA<MODE>(afr[(ks+1)&1], sA, wr,g,t,(ks+1)*8);
            const int k0=ks*8, cur=ks&1;
            unsigned b0p[2],b1p[2];
            { int n=wc+g;
              b0p[0]=__float_as_uint(sB[n*36+k0+t]);
              b1p[0]=__float_as_uint(sB[n*36+k0+4+t]); }
            #pragma unroll
            for(int j=0;j<8;j++){
                if(j<7){
                    int n=wc+(j+1)*8+g;
                    b0p[(j+1)&1]=__float_as_uint(sB[n*36+k0+t]);
                    b1p[(j+1)&1]=__float_as_uint(sB[n*36+k0+4+t]);
                }
                #pragma unroll
                for(int rb=0;rb<4;rb++)
                    mma8(acc[rb][j],afr[cur][rb][0],afr[cur][rb][1],afr[cur][rb][2],afr[cur][rb][3],
                         b0p[j&1],b1p[j&1]);
            }
        }
        __syncthreads();
    }
    #pragma unroll
    for(int rb=0;rb<4;rb++){
      #pragma unroll
      for(int j=0;j<8;j++){
        int n=n0+wc+j*8+2*t;
        #pragma unroll
        for(int h2=0;h2<2;h2++){
            int r=m0+wr+rb*16+g+h2*8;
            float2 v;
            if(MODE==2){
                v.x=acc[rb][j][h2*2]+bias[n]; v.y=acc[rb][j][h2*2+1]+bias[n+1];
                if(rmask[r]!=0u){ v.x=0.f; v.y=0.f; }
                *(float2*)&Cp[(size_t)r*512+n]=v;
            } else {
                v.x=to_tf32(acc[rb][j][h2*2]); v.y=to_tf32(acc[rb][j][h2*2+1]);
                if(MODE==0){
                    if(n<512) *(float2*)&g_k[(size_t)r*512+n]=v;
                    else      *(float2*)&g_v[(size_t)r*512+(n-512)]=v;
                } else *(float2*)&g_q[(size_t)r*512+n]=v;
            }
        }
      }
    }
}

// One CTA per (batch, head). 512 thr = 16 warps, warp tile 16x16.
// All inputs pre-rounded -> no cvt in mma paths. cp.async: {Q,K} then {V}.
__global__ __launch_bounds__(512,1)
void attn_kernel(const unsigned* __restrict__ pmask)
{
    extern __shared__ float sm[];
    float* sQ = sm;                  // 32x132
    float* sK = sQ + 32*132;         // 128x132
    float* sV = sK + 128*132;        // 128x128, natural [e][d], XOR-swizzled cols
    float* sL = sV + 128*128;        // 32x132
    int b=blockIdx.x, h=blockIdx.y;
    int tid=threadIdx.x, warp=tid>>5, lane=tid&31, g=lane>>2, t=lane&3;
    const float* Qg = g_q + ((size_t)b*32 )*512 + h*128;
    const float* Kg = g_k + ((size_t)b*128)*512 + h*128;
    const float* Vg = g_v + ((size_t)b*128)*512 + h*128;

    #pragma unroll
    for(int u=0;u<2;u++){
        int i=tid+u*512, r=i>>5, c4=(i&31)*4;
        cpa16(&sQ[r*132+c4], &Qg[(size_t)r*512+c4]);
    }
    #pragma unroll
    for(int u=0;u<8;u++){
        int i=tid+u*512, r=i>>5, c4=(i&31)*4;
        cpa16(&sK[r*132+c4], &Kg[(size_t)r*512+c4]);
    }
    CP_COMMIT();
    #pragma unroll
    for(int u=0;u<8;u++){
        int i=tid+u*512, k=i>>5, c4=(i&31)*4;
        cpa16(&sV[k*128 + (c4 ^ ((k&3)<<3))], &Vg[(size_t)k*512+c4]);
    }
    CP_COMMIT();
    CP_WAIT(1);
    __syncthreads();

    int r0=(warp>>3)*16, n0=(warp&7)*16;
    // ---- logits = Q @ K^T ----
    float cl[2][4]={};
    #pragma unroll
    for(int kk=0;kk<16;kk++){
        int k0=kk*8, r=r0+g;
        unsigned a0=__float_as_uint(sQ[r*132+k0+t]);
        unsigned a1=__float_as_uint(sQ[(r+8)*132+k0+t]);
        unsigned a2=__float_as_uint(sQ[r*132+k0+4+t]);
        unsigned a3=__float_as_uint(sQ[(r+8)*132+k0+4+t]);
        #pragma unroll
        for(int j=0;j<2;j++){
            int n=n0+j*8+g;
            unsigned b0=__float_as_uint(sK[n*132+k0+t]);
            unsigned b1=__float_as_uint(sK[n*132+k0+4+t]);
            mma8(cl[j],a0,a1,a2,a3,b0,b1);
        }
    }
    const float scale=0.08838834764831845f;
    const unsigned* pm = pmask + (size_t)b*32*128;
    #pragma unroll
    for(int j=0;j<2;j++){
        int n=n0+j*8+2*t;
        #pragma unroll
        for(int h2=0;h2<2;h2++){
            int r=r0+g+h2*8;
            float x0=cl[j][h2*2]*scale, x1=cl[j][h2*2+1]*scale;
            if(pm[r*128+n  ]!=0u) x0=NEG_INF;
            if(pm[r*128+n+1]!=0u) x1=NEG_INF;
            sL[r*132+n]=x0; sL[r*132+n+1]=x1;
        }
    }
    __syncthreads();
    // ---- softmax: 2 rows per warp ----
    #pragma unroll
    for(int rr=0;rr<2;rr++){
        int r=warp*2+rr;
        float x[4];
        #pragma unroll
        for(int i2=0;i2<4;i2++) x[i2]=sL[r*132+lane+32*i2];
        float m=fmaxf(fmaxf(x[0],x[1]),fmaxf(x[2],x[3]));
        #pragma unroll
        for(int o=16;o>0;o>>=1) m=fmaxf(m,__shfl_xor_sync(0xffffffffu,m,o));
        bool dead=(m==NEG_INF);
        float p[4], s=0.f;
        #pragma unroll
        for(int i2=0;i2<4;i2++){ p[i2]=dead?0.f:__expf(x[i2]-m); s+=p[i2]; }
        #pragma unroll
        for(int o=16;o>0;o>>=1) s+=__shfl_xor_sync(0xffffffffu,s,o);
        float inv=(s>0.f)?(1.f/s):0.f;
        #pragma unroll
        for(int i2=0;i2<4;i2++) sL[r*132+lane+32*i2]=to_tf32(p[i2]*inv);
    }
    CP_WAIT(0);
    __syncthreads();
    // ---- out = P @ V ----
    float co[2][4]={};
    #pragma unroll
    for(int kk=0;kk<16;kk++){
        int k0=kk*8, r=r0+g;
        unsigned a0=__float_as_uint(sL[r*132+k0+t]);
        unsigned a1=__float_as_uint(sL[(r+8)*132+k0+t]);
        unsigned a2=__float_as_uint(sL[r*132+k0+4+t]);
        unsigned a3=__float_as_uint(sL[(r+8)*132+k0+4+t]);
        #pragma unroll
        for(int j=0;j<2;j++){
            int n=(n0+j*8+g) ^ (t<<3);
            unsigned b0=__float_as_uint(sV[(k0+t  )*128 + n]);
            unsigned b1=__float_as_uint(sV[(k0+4+t)*128 + n]);
            mma8(co[j],a0,a1,a2,a3,b0,b1);
        }
    }
    #pragma unroll
    for(int j=0;j<2;j++){
        int n=n0+j*8+2*t;
        #pragma unroll
        for(int h2=0;h2<2;h2++){
            int r=r0+g+h2*8;
            float2 v; v.x=to_tf32(co[j][h2*2]); v.y=to_tf32(co[j][h2*2+1]);
            *(float2*)&g_attn[((size_t)b*32+r)*512 + h*128 + n]=v;
        }
    }
}

extern "C" void kernel_launch(void* const* d_in, const int* in_sizes, int n_in,
                              void* d_out, int out_size)
{
    const float*    ent   = (const float*)d_in[0];
    const unsigned* pmask = (const unsigned*)d_in[1];
    const unsigned* post  = (const unsigned*)d_in[2];
    const float*    Win   = (const float*)d_in[3];
    const float*    Wout  = (const float*)d_in[4];
    const float*    bout  = (const float*)d_in[5];
    float*          out   = (float*)d_out;
    (void)in_sizes; (void)n_in; (void)out_size;

    cudaFuncSetAttribute(gemm2<0,256>, cudaFuncAttributeMaxDynamicSharedMemorySize, SMEM_GEMM);
    cudaFuncSetAttribute(gemm2<1,256>, cudaFuncAttributeMaxDynamicSharedMemorySize, SMEM_GEMM);
    cudaFuncSetAttribute(gemm2<2,512>, cudaFuncAttributeMaxDynamicSharedMemorySize, SMEM_GEMM);
    cudaFuncSetAttribute(attn_kernel,  cudaFuncAttributeMaxDynamicSharedMemorySize, SMEM_ATTN);

    // K0: round weights to tf32 once
    prep_w<<<384,256>>>(Win, Wout);
    // K1a: K/V projection  [524288 x 1024]
    gemm2<0,256><<<dim3(8,4096),128,SMEM_GEMM>>>(ent, nullptr, nullptr, nullptr);
    // K1b: Q projection    [131072 x 512] (gathered rows)
    gemm2<1,256><<<dim3(4,1024),128,SMEM_GEMM>>>(ent, nullptr, nullptr, nullptr);
    // K2: per-(batch,head) masked attention
    attn_kernel<<<dim3(4096,4),512,SMEM_ATTN>>>(pmask);
    // K3: out projection + bias + post-mask
    gemm2<2,512><<<dim3(4,1024),128,SMEM_GEMM>>>(nullptr, out, bout, post);
}